// round 6
// baseline (speedup 1.0000x reference)
#include <cuda_runtime.h>
#include <math.h>

#define NPTS 262144
#define HID 128
#define CTXD 128
#define NSTEPS 50
#define ZD 2
#define AS_LD 129   // odd stride -> conflict-free scalar smem access

// output layout: traj (51,N,2) | us (50,N,2) | times (51)
#define OUT_US    ((size_t)(NSTEPS + 1) * NPTS * ZD)
#define OUT_TIMES (OUT_US + (size_t)NSTEPS * NPTS * ZD)

__device__ float g_dctx[NPTS * HID];   // posterior_ctx @ dW1[2:130] + db1
__device__ float g_cctx[NPTS * HID];   // cnf_ctx @ cW1[2:130] + cb1
__device__ float g_tvd[NSTEPS * HID];  // temb @ dW1[130:162]
__device__ float g_tvc[NSTEPS * HID];
__device__ float g_dt[NSTEPS];
__device__ float g_gs[NSTEPS];         // g_base*(1-t_i)*sqrt(max(dt,1e-12))

__device__ __forceinline__ float siluf(float x) {
    return __fdividef(x, 1.0f + __expf(-x));
}

// 64x128 @ 128x128 register-tiled GEMM core using packed fp32x2 FMA.
// Thread tile: 4 rows x 8 cols (4 f32x2 pairs).
__device__ __forceinline__ void gemm_core(const float* __restrict__ As,
                                          const float* __restrict__ Ws,
                                          int r0, int c0,
                                          unsigned long long (&acc)[4][4]) {
#pragma unroll
    for (int i = 0; i < 4; ++i)
#pragma unroll
        for (int j = 0; j < 4; ++j) acc[i][j] = 0ull;

#pragma unroll 4
    for (int k = 0; k < HID; ++k) {
        unsigned long long h[4];
#pragma unroll
        for (int i = 0; i < 4; ++i) {
            unsigned v = __float_as_uint(As[(r0 + i) * AS_LD + k]);
            asm("mov.b64 %0, {%1, %1};" : "=l"(h[i]) : "r"(v));
        }
        const float* wr = Ws + k * HID + c0;
        ulonglong2 wa = *(const ulonglong2*)(wr);       // LDS.128
        ulonglong2 wb = *(const ulonglong2*)(wr + 4);
        unsigned long long w0 = wa.x, w1 = wa.y, w2 = wb.x, w3 = wb.y;
#pragma unroll
        for (int i = 0; i < 4; ++i) {
            asm("fma.rn.f32x2 %0, %1, %2, %0;" : "+l"(acc[i][0]) : "l"(h[i]), "l"(w0));
            asm("fma.rn.f32x2 %0, %1, %2, %0;" : "+l"(acc[i][1]) : "l"(h[i]), "l"(w1));
            asm("fma.rn.f32x2 %0, %1, %2, %0;" : "+l"(acc[i][2]) : "l"(h[i]), "l"(w2));
            asm("fma.rn.f32x2 %0, %1, %2, %0;" : "+l"(acc[i][3]) : "l"(h[i]), "l"(w3));
        }
    }
}

// ---------------- precompute: ctx @ W1[2:130] + b1 ----------------
__global__ void __launch_bounds__(256, 2)
ctx_kernel(const float* __restrict__ X, const float* __restrict__ W1,
           const float* __restrict__ b1, int which) {
    extern __shared__ float sm[];
    float* Ws = sm;               // 128*128
    float* Xs = sm + HID * HID;   // 64*AS_LD
    float* out = which ? g_cctx : g_dctx;
    int tid = threadIdx.x;
    size_t row0 = (size_t)blockIdx.x * 64;

    for (int i = tid; i < HID * HID; i += 256) Ws[i] = W1[2 * HID + i];
#pragma unroll 4
    for (int i = tid; i < 64 * HID; i += 256) {
        int r = i >> 7, c = i & 127;
        Xs[r * AS_LD + c] = X[(row0 + r) * HID + c];
    }
    __syncthreads();

    int rg = tid >> 4, cg = tid & 15;
    int r0 = rg * 4, c0 = cg * 8;
    unsigned long long acc[4][4];
    gemm_core(Xs, Ws, r0, c0, acc);

#pragma unroll
    for (int i = 0; i < 4; ++i) {
        size_t base = (row0 + r0 + i) * HID + c0;
#pragma unroll
        for (int j = 0; j < 4; ++j) {
            unsigned lo, hi;
            asm("mov.b64 {%0, %1}, %2;" : "=r"(lo), "=r"(hi) : "l"(acc[i][j]));
            float2 v;
            v.x = __uint_as_float(lo) + b1[c0 + 2 * j];
            v.y = __uint_as_float(hi) + b1[c0 + 2 * j + 1];
            *(float2*)&out[base + 2 * j] = v;
        }
    }
}

// ---------------- per-step constants (tiny) ----------------
__global__ void __launch_bounds__(128)
step_const_kernel(const float* __restrict__ times, const float* __restrict__ freqs,
                  const float* __restrict__ dW1, const float* __restrict__ cW1,
                  const float* __restrict__ logd, float* __restrict__ out) {
    int s = blockIdx.x;
    int t = threadIdx.x;
    __shared__ float temb[32];
    float t_i = times[s];
    if (t < 32) {
        float a = 6.28318530717958647692f * t_i * freqs[t & 15];
        temb[t] = (t < 16) ? sinf(a) : cosf(a);
    }
    __syncthreads();
    if (t < HID) {
        float sd = 0.0f, sc = 0.0f;
#pragma unroll
        for (int k = 0; k < 32; ++k) {
            sd += temb[k] * dW1[(2 + CTXD + k) * HID + t];
            sc += temb[k] * cW1[(2 + CTXD + k) * HID + t];
        }
        g_tvd[s * HID + t] = sd;
        g_tvc[s * HID + t] = sc;
    }
    if (t == 0) {
        float dt = times[s + 1] - t_i;
        float gb = log1pf(expf(logd[0]));   // softplus, DIFFUSION_SCALE=1
        g_dt[s] = dt;
        g_gs[s] = gb * (1.0f - t_i) * sqrtf(fmaxf(dt, 1e-12f));
    }
    if (s == 0 && t < NSTEPS + 1) out[OUT_TIMES + t] = times[t];
}

// ---------------- main: 50-step SDE loop, 64 rows per CTA ----------------
__global__ void __launch_bounds__(256, 1)
sde_kernel(const float* __restrict__ z0, const float* __restrict__ noise,
           const float* __restrict__ dW1, const float* __restrict__ dW2,
           const float* __restrict__ db2, const float* __restrict__ dW3,
           const float* __restrict__ db3,
           const float* __restrict__ cW1, const float* __restrict__ cW2,
           const float* __restrict__ cb2, const float* __restrict__ cW3,
           const float* __restrict__ cb3,
           float* __restrict__ out) {
    extern __shared__ float sm[];
    float* W2ds = sm;                       // 16384
    float* W2cs = W2ds + HID * HID;         // 16384
    float* As   = W2cs + HID * HID;         // 64*129
    float* Bs   = As + 64 * AS_LD;          // 64*129
    float* w1zd = Bs + 64 * AS_LD;          // 256 (dW1 rows 0..1)
    float* w1zc = w1zd + 256;               // 256
    float* w3ds = w1zc + 256;               // 256 (dW3 [128][2])
    float* w3cs = w3ds + 256;               // 256
    float* b2ds = w3cs + 256;               // 128
    float* b2cs = b2ds + 128;               // 128
    float* tvds = b2cs + 128;               // 128
    float* tvcs = tvds + 128;               // 128
    float* zsm  = tvcs + 128;               // 128 (64 rows x 2)
    float* b3s  = zsm + 128;                // 4

    int tid = threadIdx.x;
    size_t row0 = (size_t)blockIdx.x * 64;

    for (int i = tid; i < HID * HID; i += 256) { W2ds[i] = dW2[i]; W2cs[i] = cW2[i]; }
    w1zd[tid] = dW1[tid]; w1zc[tid] = cW1[tid];
    w3ds[tid] = dW3[tid]; w3cs[tid] = cW3[tid];
    if (tid < 128) { b2ds[tid] = db2[tid]; b2cs[tid] = cb2[tid]; }
    if (tid < 2)   { b3s[tid] = db3[tid];  b3s[2 + tid] = cb3[tid]; }
    if (tid < 128) {
        float zv = z0[row0 * 2 + tid];
        zsm[tid] = zv;
        out[row0 * 2 + tid] = zv;           // traj[0] = z0
    }
    __syncthreads();

    int rg = tid >> 4, cg = tid & 15;
    int r0 = rg * 4, c0 = cg * 8;

    for (int s = 0; s < NSTEPS; ++s) {
        if (tid < 128) tvds[tid] = g_tvd[s * HID + tid];
        else           tvcs[tid - 128] = g_tvc[s * HID + tid - 128];
        float dt  = g_dt[s];
        float gsc = g_gs[s];
        __syncthreads();

        // layer1, diffusion net -> As
#pragma unroll 8
        for (int i = tid; i < 64 * HID; i += 256) {
            int r = i >> 7, c = i & 127;
            float x = g_dctx[(row0 + r) * HID + c] + tvds[c]
                    + zsm[r * 2] * w1zd[c] + zsm[r * 2 + 1] * w1zd[HID + c];
            As[r * AS_LD + c] = siluf(x);
        }
        __syncthreads();

        // layer2, diffusion: Bs = silu(As @ W2d + db2)
        unsigned long long acc[4][4];
        gemm_core(As, W2ds, r0, c0, acc);
#pragma unroll
        for (int i = 0; i < 4; ++i)
#pragma unroll
            for (int j = 0; j < 4; ++j) {
                unsigned lo, hi;
                asm("mov.b64 {%0, %1}, %2;" : "=r"(lo), "=r"(hi) : "l"(acc[i][j]));
                Bs[(r0 + i) * AS_LD + c0 + 2 * j]     = siluf(__uint_as_float(lo) + b2ds[c0 + 2 * j]);
                Bs[(r0 + i) * AS_LD + c0 + 2 * j + 1] = siluf(__uint_as_float(hi) + b2ds[c0 + 2 * j + 1]);
            }
        __syncthreads();

        // layer1, cnf net -> As (overwrite)
#pragma unroll 8
        for (int i = tid; i < 64 * HID; i += 256) {
            int r = i >> 7, c = i & 127;
            float x = g_cctx[(row0 + r) * HID + c] + tvcs[c]
                    + zsm[r * 2] * w1zc[c] + zsm[r * 2 + 1] * w1zc[HID + c];
            As[r * AS_LD + c] = siluf(x);
        }
        __syncthreads();

        // layer2, cnf: As = silu(As @ W2c + cb2)  (read all, sync, write in place)
        gemm_core(As, W2cs, r0, c0, acc);
        __syncthreads();
#pragma unroll
        for (int i = 0; i < 4; ++i)
#pragma unroll
            for (int j = 0; j < 4; ++j) {
                unsigned lo, hi;
                asm("mov.b64 {%0, %1}, %2;" : "=r"(lo), "=r"(hi) : "l"(acc[i][j]));
                As[(r0 + i) * AS_LD + c0 + 2 * j]     = siluf(__uint_as_float(lo) + b2cs[c0 + 2 * j]);
                As[(r0 + i) * AS_LD + c0 + 2 * j + 1] = siluf(__uint_as_float(hi) + b2cs[c0 + 2 * j + 1]);
            }
        __syncthreads();

        // layer3 + SDE update: one thread per (row, dim)
        if (tid < 128) {
            int r = tid >> 1, d = tid & 1;
            float au = b3s[d], af = b3s[2 + d];
#pragma unroll 8
            for (int j = 0; j < HID; ++j) {
                au += Bs[r * AS_LD + j] * w3ds[j * 2 + d];   // u (diffusion)
                af += As[r * AS_LD + j] * w3cs[j * 2 + d];   // f_theta (cnf)
            }
            size_t gi = row0 * 2 + tid;
            float xi = noise[(size_t)s * ((size_t)NPTS * ZD) + gi];
            float zn = zsm[tid] + (af + au) * dt + xi * gsc;
            out[OUT_US + (size_t)s * ((size_t)NPTS * ZD) + gi] = au;  // us[s]
            out[(size_t)(s + 1) * ((size_t)NPTS * ZD) + gi]    = zn;  // traj[s+1]
            zsm[tid] = zn;
        }
        // next-iteration leading __syncthreads gates all hazards
    }
}

extern "C" void kernel_launch(void* const* d_in, const int* in_sizes, int n_in,
                              void* d_out, int out_size) {
    (void)in_sizes; (void)n_in; (void)out_size;
    const float* z0    = (const float*)d_in[0];
    const float* pctx  = (const float*)d_in[1];
    const float* cctx  = (const float*)d_in[2];
    const float* times = (const float*)d_in[3];
    const float* noise = (const float*)d_in[4];
    const float* freqs = (const float*)d_in[5];
    const float* dW1   = (const float*)d_in[6];
    const float* db1   = (const float*)d_in[7];
    const float* dW2   = (const float*)d_in[8];
    const float* db2   = (const float*)d_in[9];
    const float* dW3   = (const float*)d_in[10];
    const float* db3   = (const float*)d_in[11];
    const float* cW1   = (const float*)d_in[12];
    const float* cb1   = (const float*)d_in[13];
    const float* cW2   = (const float*)d_in[14];
    const float* cb2   = (const float*)d_in[15];
    const float* cW3   = (const float*)d_in[16];
    const float* cb3   = (const float*)d_in[17];
    const float* logd  = (const float*)d_in[18];
    float* out = (float*)d_out;

    const int CTX_SMEM  = (HID * HID + 64 * AS_LD) * (int)sizeof(float);
    const int MAIN_SMEM = (2 * HID * HID + 2 * 64 * AS_LD + 4 * 256
                           + 2 * 128 + 2 * 128 + 128 + 8) * (int)sizeof(float);

    static int attr_done = 0;
    if (!attr_done) {
        cudaFuncSetAttribute(ctx_kernel, cudaFuncAttributeMaxDynamicSharedMemorySize, CTX_SMEM);
        cudaFuncSetAttribute(sde_kernel, cudaFuncAttributeMaxDynamicSharedMemorySize, MAIN_SMEM);
        attr_done = 1;
    }

    step_const_kernel<<<NSTEPS, 128>>>(times, freqs, dW1, cW1, logd, out);
    ctx_kernel<<<NPTS / 64, 256, CTX_SMEM>>>(pctx, dW1, db1, 0);
    ctx_kernel<<<NPTS / 64, 256, CTX_SMEM>>>(cctx, cW1, cb1, 1);
    sde_kernel<<<NPTS / 64, 256, MAIN_SMEM>>>(z0, noise, dW1, dW2, db2, dW3, db3,
                                              cW1, cW2, cb2, cW3, cb3, out);
}